// round 4
// baseline (speedup 1.0000x reference)
#include <cuda_runtime.h>
#include <cstdint>
#include <math.h>

// SpatialGlimpse fused, persistent CTAs + double-buffered TMA pipeline.
// Phase A: horizontal (K+1)-tap weighted sums (conflict-free LDS.128),
// Phase B: vertical (K+1)-tap weighted sum. Prefetch tile n+1 during compute(n).

static constexpr int BATCH  = 64;
static constexpr int H = 512, W = 512, C = 3;
static constexpr int OUTHW  = 64;
static constexpr int NDEPTH = 3;
static constexpr int ROWFL  = W * C;   // 1536 floats per image row
static constexpr int NT     = 256;

template<int K> struct Cfg;
template<> struct Cfg<1> { static constexpr int TILE_I = 8; static constexpr int ROWF = 204; static constexpr int NV = 3; };
template<> struct Cfg<2> { static constexpr int TILE_I = 4; static constexpr int ROWF = 396; static constexpr int NV = 3; };
template<> struct Cfg<4> { static constexpr int TILE_I = 2; static constexpr int ROWF = 780; static constexpr int NV = 5; };
// IR = TILE_I*K + 1 = 9 input rows for every depth.

// Persistent grid: 3 CTAs/SM x 152 SMs. Group sizes balance bytes/CTA (~165KB each).
static constexpr int G4 = 348, G2 = 86, G1 = 22;
static constexpr int NC = G4 + G2 + G1;          // 456

// SMEM floats: [0,8) two mbarriers (16B apart) | buf0 | buf1 | hs (float4)
static constexpr int SMEM_MAX = (8 + 2 * 9 * Cfg<4>::ROWF + 9 * OUTHW * 4) * 4;  // 65408 B

__device__ __forceinline__ uint32_t smem_u32(const void* p) {
    return (uint32_t)__cvta_generic_to_shared(p);
}
__device__ __forceinline__ void mbar_init(uint32_t a, uint32_t cnt) {
    asm volatile("mbarrier.init.shared.b64 [%0], %1;" :: "r"(a), "r"(cnt) : "memory");
}
__device__ __forceinline__ void mbar_expect_tx(uint32_t a, uint32_t bytes) {
    asm volatile("mbarrier.arrive.expect_tx.shared.b64 _, [%0], %1;" :: "r"(a), "r"(bytes) : "memory");
}
__device__ __forceinline__ void mbar_wait(uint32_t a, uint32_t parity) {
    asm volatile(
        "{\n\t"
        ".reg .pred P;\n\t"
        "LAB_WAIT_%=:\n\t"
        "mbarrier.try_wait.parity.acquire.cta.shared::cta.b64 P, [%0], %1, 0x989680;\n\t"
        "@P bra LAB_DONE_%=;\n\t"
        "bra LAB_WAIT_%=;\n\t"
        "LAB_DONE_%=:\n\t"
        "}"
        :: "r"(a), "r"(parity) : "memory");
}
__device__ __forceinline__ void bulk_g2s(uint32_t dst, const void* src, uint32_t bytes, uint32_t mbar) {
    asm volatile(
        "cp.async.bulk.shared::cluster.global.mbarrier::complete_tx::bytes [%0], [%1], %2, [%3];"
        :: "r"(dst), "l"(src), "r"(bytes), "r"(mbar) : "memory");
}

// Horizontal weighted sum for one (row, j): window of K+1 pixels x 3 channels.
// SH = sub-float4 shift (compile-time so v[] stays in registers).
template<int K, int SH>
__device__ __forceinline__ void hreduce_one(const float* __restrict__ rowp, float wx, float4& h)
{
    constexpr int NV = Cfg<K>::NV;
    const float hx0 = 1.0f - wx;
    float v[4 * NV];
    const float4* rp = reinterpret_cast<const float4*>(rowp);
#pragma unroll
    for (int t = 0; t < NV; t++) {
        float4 q = rp[t];
        v[4*t+0] = q.x; v[4*t+1] = q.y; v[4*t+2] = q.z; v[4*t+3] = q.w;
    }
    float r0 = hx0 * v[SH + 0] + wx * v[SH + 3*K + 0];
    float r1 = hx0 * v[SH + 1] + wx * v[SH + 3*K + 1];
    float r2 = hx0 * v[SH + 2] + wx * v[SH + 3*K + 2];
#pragma unroll
    for (int q = 1; q < K; q++) {
        r0 += v[SH + 3*q + 0];
        r1 += v[SH + 3*q + 1];
        r2 += v[SH + 3*q + 2];
    }
    h.x = r0; h.y = r1; h.z = r2; h.w = 0.0f;
}

template<int K, int D>
__device__ __forceinline__ void run_group(
    const float* __restrict__ img, const float* __restrict__ offs,
    float* __restrict__ out, float* smem, int cid, int G)
{
    constexpr int TILE_I = Cfg<K>::TILE_I;
    constexpr int RF     = Cfg<K>::ROWF;
    constexpr int IR     = TILE_I * K + 1;     // 9
    constexpr int SPAN   = OUTHW * K + 1;
    constexpr int TPI    = OUTHW / TILE_I;     // tiles per image
    constexpr int TILES  = BATCH * TPI;

    const int tid = threadIdx.x;
    float* buf0 = smem + 8;
    float* buf1 = smem + 8 + IR * RF;
    float4* hs  = reinterpret_cast<float4*>(smem + 8 + 2 * IR * RF);
    const uint32_t mb0 = smem_u32(smem);
    const uint32_t mb1 = smem_u32(smem + 4);

    if (tid == 0) {
        mbar_init(mb0, 1);
        mbar_init(mb1, 1);
        asm volatile("fence.proxy.async.shared::cta;" ::: "memory");
    }
    __syncthreads();

    const int ntile = (TILES - cid + G - 1) / G;   // cid < G <= TILES always

    // Stage tile t into slot: zero tails/OOB rows, then tid0 issues expect_tx + bulk copies.
    auto setup = [&](int t, int slot) {
        const int b  = t / TPI;
        const int i0 = (t % TPI) * TILE_I;
        const float cy = (offs[2*b + 0] + 1.0f) * (H * 0.5f);
        const float cx = (offs[2*b + 1] + 1.0f) * (W * 0.5f);
        const float Ey = cy - (OUTHW * K - 1) * 0.5f;
        const float Ex = cx - (OUTHW * K - 1) * 0.5f;
        const int   y0 = (int)floorf(Ey);
        const int   x0 = (int)floorf(Ex);
        const int x_hi    = min(x0 + SPAN, W);
        const int start_f = (x0 * 3) & ~3;
        const int end_f   = min((x_hi * 3 + 3) & ~3, ROWFL);
        const int validf  = end_f - start_f;
        const int rowbytes = validf * 4;
        const int ytop    = y0 + i0 * K;
        float* bp = slot ? buf1 : buf0;

        // Zero tails (disjoint from bulk-copy bytes) and any y>=H rows.
        const int ntail = RF - validf;
        for (int idx = tid; idx < IR * ntail; idx += NT) {
            const int r = idx / ntail;
            bp[r * RF + validf + idx % ntail] = 0.0f;
        }
#pragma unroll
        for (int r = 0; r < IR; r++) {
            if (ytop + r >= H) {
                for (int f = tid; f < validf; f += NT) bp[r * RF + f] = 0.0f;
            }
        }
        if (tid == 0) {
            int nvalid = 0;
#pragma unroll
            for (int r = 0; r < IR; r++) if (ytop + r < H) nvalid++;
            const uint32_t mb = slot ? mb1 : mb0;
            mbar_expect_tx(mb, (uint32_t)(nvalid * rowbytes));
#pragma unroll
            for (int r = 0; r < IR; r++) {
                const int gy = ytop + r;
                if (gy < H) {
                    const float* src = img + ((size_t)b * H + gy) * ROWFL + start_f;
                    bulk_g2s(smem_u32(bp + r * RF), src, (uint32_t)rowbytes, mb);
                }
            }
        }
    };

    setup(cid, 0);

    for (int n = 0; n < ntile; n++) {
        const int t = cid + n * G;
        if (n + 1 < ntile) setup(t + G, (n + 1) & 1);

        mbar_wait((n & 1) ? mb1 : mb0, (n >> 1) & 1);

        // Recompute geometry for tile t (cheap, avoids carrying state).
        const int b  = t / TPI;
        const int i0 = (t % TPI) * TILE_I;
        const float cy = (offs[2*b + 0] + 1.0f) * (H * 0.5f);
        const float cx = (offs[2*b + 1] + 1.0f) * (W * 0.5f);
        const float Ey = cy - (OUTHW * K - 1) * 0.5f;
        const float Ex = cx - (OUTHW * K - 1) * 0.5f;
        const int   y0 = (int)floorf(Ey);
        const int   x0 = (int)floorf(Ex);
        const float wy = Ey - (float)y0;
        const float wx = Ex - (float)x0;
        const int start_f = (x0 * 3) & ~3;
        const int off0    = x0 * 3 - start_f;        // 0..3
        float* tile = (n & 1) ? buf1 : buf0;

        // ── Phase A: horizontal reduction, one thread per (row, j). Conflict-free. ──
        {
            const int j = tid & 63;
            const int sidx = off0 + 3 * K * j;
            const int a0   = sidx & ~3;
            const int sh   = sidx & 3;
#pragma unroll
            for (int r0 = 0; r0 < IR; r0 += NT / 64) {
                const int r = r0 + (tid >> 6);
                if (r < IR) {
                    const float* rowp = tile + r * RF + a0;
                    float4 h;
                    switch (sh) {
                    case 0:  hreduce_one<K,0>(rowp, wx, h); break;
                    case 1:  hreduce_one<K,1>(rowp, wx, h); break;
                    case 2:  hreduce_one<K,2>(rowp, wx, h); break;
                    default: hreduce_one<K,3>(rowp, wx, h); break;
                    }
                    hs[r * 64 + j] = h;
                }
            }
        }
        __syncthreads();

        // ── Phase B: vertical reduction over hs. Conflict-free. ──
        constexpr float inv = 1.0f / (K * K);
        const float wy0 = 1.0f - wy;
        for (int o = tid; o < TILE_I * OUTHW; o += NT) {
            const int ti = o >> 6;
            const int j  = o & 63;
            float4 a = hs[(ti * K) * 64 + j];
            float o0 = wy0 * a.x, o1 = wy0 * a.y, o2 = wy0 * a.z;
#pragma unroll
            for (int p = 1; p < K; p++) {
                float4 m = hs[(ti * K + p) * 64 + j];
                o0 += m.x; o1 += m.y; o2 += m.z;
            }
            float4 e = hs[(ti * K + K) * 64 + j];
            o0 += wy * e.x; o1 += wy * e.y; o2 += wy * e.z;

            const size_t ob = (((size_t)b * OUTHW + (i0 + ti)) * OUTHW + j) * (C * NDEPTH);
            out[ob + 0 * NDEPTH + D] = o0 * inv;
            out[ob + 1 * NDEPTH + D] = o1 * inv;
            out[ob + 2 * NDEPTH + D] = o2 * inv;
        }
        __syncthreads();   // hs + buffer slot reuse guard
    }
}

__global__ __launch_bounds__(NT)
void glimpse_fused(const float* __restrict__ img, const float* __restrict__ offs,
                   float* __restrict__ out)
{
    extern __shared__ float smem[];
    const int cid = blockIdx.x;
    if (cid < G4) {
        run_group<4, 2>(img, offs, out, smem, cid, G4);
    } else if (cid < G4 + G2) {
        run_group<2, 1>(img, offs, out, smem, cid - G4, G2);
    } else {
        run_group<1, 0>(img, offs, out, smem, cid - G4 - G2, G1);
    }
}

extern "C" void kernel_launch(void* const* d_in, const int* in_sizes, int n_in,
                              void* d_out, int out_size)
{
    (void)in_sizes; (void)n_in; (void)out_size;
    const float* img  = (const float*)d_in[0];
    const float* offs = (const float*)d_in[1];
    float* out = (float*)d_out;

    cudaFuncSetAttribute(glimpse_fused, cudaFuncAttributeMaxDynamicSharedMemorySize, SMEM_MAX);
    glimpse_fused<<<NC, NT, SMEM_MAX>>>(img, offs, out);
}

// round 5
// speedup vs baseline: 1.3031x; 1.3031x over previous
#include <cuda_runtime.h>
#include <cstdint>
#include <math.h>

// SpatialGlimpse fused: persistent CTAs + PIPE-deep TMA prefetch pipeline.
// Phase A: horizontal (K+1)-tap weighted sums (conflict-free LDS.128),
// Phase B: vertical (K+1)-tap weighted sum.
// R5: groups sized ~tiles/CTA-uniform (fixes R4's K=1 serial tail), PIPE=3 for K<=2.

static constexpr int BATCH  = 64;
static constexpr int H = 512, W = 512, C = 3;
static constexpr int OUTHW  = 64;
static constexpr int NDEPTH = 3;
static constexpr int ROWFL  = W * C;   // 1536 floats per image row
static constexpr int NT     = 256;

template<int K> struct Cfg;
template<> struct Cfg<1> { static constexpr int TILE_I = 8; static constexpr int ROWF = 204; static constexpr int NV = 3; };
template<> struct Cfg<2> { static constexpr int TILE_I = 4; static constexpr int ROWF = 396; static constexpr int NV = 3; };
template<> struct Cfg<4> { static constexpr int TILE_I = 2; static constexpr int ROWF = 780; static constexpr int NV = 5; };
// IR = TILE_I*K + 1 = 9 input rows for every depth.

// Persistent grid, ~3 CTAs/SM. Tiles: K4=2048, K2=1024, K1=512.
// tiles/CTA: 7.1 / 9.1 / 10.7 (latency-aware skew toward the byte-heavy K=4 group).
static constexpr int G4 = 288, G2 = 112, G1 = 48;
static constexpr int NC = G4 + G2 + G1;          // 448

// SMEM floats: [0,16) mbarriers (4B-float x4 slots, 16B stride) | PIPE bufs | hs
static constexpr int SMEM_BYTES = (16 + 2 * 9 * Cfg<4>::ROWF + 9 * OUTHW * 4) * 4;  // 65440

__device__ __forceinline__ uint32_t smem_u32(const void* p) {
    return (uint32_t)__cvta_generic_to_shared(p);
}
__device__ __forceinline__ void mbar_init(uint32_t a, uint32_t cnt) {
    asm volatile("mbarrier.init.shared.b64 [%0], %1;" :: "r"(a), "r"(cnt) : "memory");
}
__device__ __forceinline__ void mbar_expect_tx(uint32_t a, uint32_t bytes) {
    asm volatile("mbarrier.arrive.expect_tx.shared.b64 _, [%0], %1;" :: "r"(a), "r"(bytes) : "memory");
}
__device__ __forceinline__ void mbar_wait(uint32_t a, uint32_t parity) {
    asm volatile(
        "{\n\t"
        ".reg .pred P;\n\t"
        "LAB_WAIT_%=:\n\t"
        "mbarrier.try_wait.parity.acquire.cta.shared::cta.b64 P, [%0], %1, 0x989680;\n\t"
        "@P bra LAB_DONE_%=;\n\t"
        "bra LAB_WAIT_%=;\n\t"
        "LAB_DONE_%=:\n\t"
        "}"
        :: "r"(a), "r"(parity) : "memory");
}
__device__ __forceinline__ void bulk_g2s(uint32_t dst, const void* src, uint32_t bytes, uint32_t mbar) {
    asm volatile(
        "cp.async.bulk.shared::cluster.global.mbarrier::complete_tx::bytes [%0], [%1], %2, [%3];"
        :: "r"(dst), "l"(src), "r"(bytes), "r"(mbar) : "memory");
}

// Horizontal weighted sum for one (row, j): window of K+1 pixels x 3 channels.
// SH = sub-float4 shift (compile-time so v[] stays in registers).
template<int K, int SH>
__device__ __forceinline__ void hreduce_one(const float* __restrict__ rowp, float wx, float4& h)
{
    constexpr int NV = Cfg<K>::NV;
    const float hx0 = 1.0f - wx;
    float v[4 * NV];
    const float4* rp = reinterpret_cast<const float4*>(rowp);
#pragma unroll
    for (int t = 0; t < NV; t++) {
        float4 q = rp[t];
        v[4*t+0] = q.x; v[4*t+1] = q.y; v[4*t+2] = q.z; v[4*t+3] = q.w;
    }
    float r0 = hx0 * v[SH + 0] + wx * v[SH + 3*K + 0];
    float r1 = hx0 * v[SH + 1] + wx * v[SH + 3*K + 1];
    float r2 = hx0 * v[SH + 2] + wx * v[SH + 3*K + 2];
#pragma unroll
    for (int q = 1; q < K; q++) {
        r0 += v[SH + 3*q + 0];
        r1 += v[SH + 3*q + 1];
        r2 += v[SH + 3*q + 2];
    }
    h.x = r0; h.y = r1; h.z = r2; h.w = 0.0f;
}

template<int K, int D, int PIPE>
__device__ __forceinline__ void run_group(
    const float* __restrict__ img, const float* __restrict__ offs,
    float* __restrict__ out, float* smem, int cid, int G)
{
    constexpr int TILE_I = Cfg<K>::TILE_I;
    constexpr int RF     = Cfg<K>::ROWF;
    constexpr int IR     = TILE_I * K + 1;     // 9
    constexpr int SPAN   = OUTHW * K + 1;
    constexpr int TPI    = OUTHW / TILE_I;     // tiles per image
    constexpr int TILES  = BATCH * TPI;

    const int tid = threadIdx.x;
    float* bufs = smem + 16;                   // PIPE buffers of IR*RF floats
    float4* hs  = reinterpret_cast<float4*>(smem + 16 + PIPE * IR * RF);

    if (tid == 0) {
#pragma unroll
        for (int p = 0; p < PIPE; p++) mbar_init(smem_u32(smem + 4 * p), 1);
        asm volatile("fence.proxy.async.shared::cta;" ::: "memory");
    }
    __syncthreads();

    const int ntile = (TILES - cid + G - 1) / G;   // cid < G <= TILES

    // Stage tile t into buffer slot: zero tails/OOB rows + tid0 issues expect_tx + bulk copies.
    auto setup = [&](int t, int slot) {
        const int b  = t / TPI;
        const int i0 = (t % TPI) * TILE_I;
        const float cy = (offs[2*b + 0] + 1.0f) * (H * 0.5f);
        const float cx = (offs[2*b + 1] + 1.0f) * (W * 0.5f);
        const float Ey = cy - (OUTHW * K - 1) * 0.5f;
        const float Ex = cx - (OUTHW * K - 1) * 0.5f;
        const int   y0 = (int)floorf(Ey);
        const int   x0 = (int)floorf(Ex);
        const int x_hi    = min(x0 + SPAN, W);
        const int start_f = (x0 * 3) & ~3;
        const int end_f   = min((x_hi * 3 + 3) & ~3, ROWFL);
        const int validf  = end_f - start_f;
        const int rowbytes = validf * 4;
        const int ytop    = y0 + i0 * K;
        float* bp = bufs + slot * IR * RF;

        // Zero tails (disjoint from bulk-copy bytes) and any y>=H rows.
        const int ntail = RF - validf;
        for (int idx = tid; idx < IR * ntail; idx += NT) {
            const int r = idx / ntail;
            bp[r * RF + validf + idx % ntail] = 0.0f;
        }
#pragma unroll
        for (int r = 0; r < IR; r++) {
            if (ytop + r >= H) {
                for (int f = tid; f < validf; f += NT) bp[r * RF + f] = 0.0f;
            }
        }
        if (tid == 0) {
            int nvalid = 0;
#pragma unroll
            for (int r = 0; r < IR; r++) if (ytop + r < H) nvalid++;
            const uint32_t mb = smem_u32(smem + 4 * slot);
            mbar_expect_tx(mb, (uint32_t)(nvalid * rowbytes));
#pragma unroll
            for (int r = 0; r < IR; r++) {
                const int gy = ytop + r;
                if (gy < H) {
                    const float* src = img + ((size_t)b * H + gy) * ROWFL + start_f;
                    bulk_g2s(smem_u32(bp + r * RF), src, (uint32_t)rowbytes, mb);
                }
            }
        }
    };

    // Prologue: fill PIPE-1 slots ahead.
#pragma unroll
    for (int p = 0; p < PIPE - 1; p++) {
        if (p < ntile) setup(cid + p * G, p);
    }

    for (int n = 0; n < ntile; n++) {
        const int t = cid + n * G;
        {
            const int np = n + PIPE - 1;
            if (np < ntile) setup(cid + np * G, np % PIPE);   // targets slot freed at iter n-1
        }

        mbar_wait(smem_u32(smem + 4 * (n % PIPE)), (n / PIPE) & 1);

        // Geometry for tile t (recomputed — cheap).
        const int b  = t / TPI;
        const int i0 = (t % TPI) * TILE_I;
        const float cy = (offs[2*b + 0] + 1.0f) * (H * 0.5f);
        const float cx = (offs[2*b + 1] + 1.0f) * (W * 0.5f);
        const float Ey = cy - (OUTHW * K - 1) * 0.5f;
        const float Ex = cx - (OUTHW * K - 1) * 0.5f;
        const int   y0 = (int)floorf(Ey);
        const int   x0 = (int)floorf(Ex);
        const float wy = Ey - (float)y0;
        const float wx = Ex - (float)x0;
        const int start_f = (x0 * 3) & ~3;
        const int off0    = x0 * 3 - start_f;        // 0..3
        float* tile = bufs + (n % PIPE) * IR * RF;

        // ── Phase A: horizontal reduction, one thread per (row, j). Conflict-free. ──
        {
            const int j = tid & 63;
            const int sidx = off0 + 3 * K * j;
            const int a0   = sidx & ~3;
            const int sh   = sidx & 3;
#pragma unroll
            for (int r0 = 0; r0 < IR; r0 += NT / 64) {
                const int r = r0 + (tid >> 6);
                if (r < IR) {
                    const float* rowp = tile + r * RF + a0;
                    float4 h;
                    switch (sh) {
                    case 0:  hreduce_one<K,0>(rowp, wx, h); break;
                    case 1:  hreduce_one<K,1>(rowp, wx, h); break;
                    case 2:  hreduce_one<K,2>(rowp, wx, h); break;
                    default: hreduce_one<K,3>(rowp, wx, h); break;
                    }
                    hs[r * 64 + j] = h;
                }
            }
        }
        __syncthreads();

        // ── Phase B: vertical reduction over hs. Conflict-free. ──
        constexpr float inv = 1.0f / (K * K);
        const float wy0 = 1.0f - wy;
        for (int o = tid; o < TILE_I * OUTHW; o += NT) {
            const int ti = o >> 6;
            const int j  = o & 63;
            float4 a = hs[(ti * K) * 64 + j];
            float o0 = wy0 * a.x, o1 = wy0 * a.y, o2 = wy0 * a.z;
#pragma unroll
            for (int p = 1; p < K; p++) {
                float4 m = hs[(ti * K + p) * 64 + j];
                o0 += m.x; o1 += m.y; o2 += m.z;
            }
            float4 e = hs[(ti * K + K) * 64 + j];
            o0 += wy * e.x; o1 += wy * e.y; o2 += wy * e.z;

            const size_t ob = (((size_t)b * OUTHW + (i0 + ti)) * OUTHW + j) * (C * NDEPTH);
            out[ob + 0 * NDEPTH + D] = o0 * inv;
            out[ob + 1 * NDEPTH + D] = o1 * inv;
            out[ob + 2 * NDEPTH + D] = o2 * inv;
        }
        __syncthreads();   // hs + buffer slot reuse guard
    }
}

__global__ __launch_bounds__(NT)
void glimpse_fused(const float* __restrict__ img, const float* __restrict__ offs,
                   float* __restrict__ out)
{
    extern __shared__ float smem[];
    const int cid = blockIdx.x;
    if (cid < G4) {
        run_group<4, 2, 2>(img, offs, out, smem, cid, G4);          // 2x28.1KB bufs
    } else if (cid < G4 + G2) {
        run_group<2, 1, 3>(img, offs, out, smem, cid - G4, G2);     // 3x14.3KB bufs
    } else {
        run_group<1, 0, 3>(img, offs, out, smem, cid - G4 - G2, G1); // 3x7.3KB bufs
    }
}

extern "C" void kernel_launch(void* const* d_in, const int* in_sizes, int n_in,
                              void* d_out, int out_size)
{
    (void)in_sizes; (void)n_in; (void)out_size;
    const float* img  = (const float*)d_in[0];
    const float* offs = (const float*)d_in[1];
    float* out = (float*)d_out;

    cudaFuncSetAttribute(glimpse_fused, cudaFuncAttributeMaxDynamicSharedMemorySize, SMEM_BYTES);
    glimpse_fused<<<NC, NT, SMEM_BYTES>>>(img, offs, out);
}

// round 6
// speedup vs baseline: 2.8989x; 2.2247x over previous
#include <cuda_runtime.h>
#include <cstdint>
#include <math.h>

// SpatialGlimpse fused, one-shot blocks (R3 structure), two-phase separable stencil.
// R6: K=4 tiles split in x (JW=32) -> max block SMEM 23.5KB -> 8 CTAs/SM (warp cap),
// 5632 blocks for deeper latency overlap. K=4 region first (K1/K2 then L2-hit).

static constexpr int BATCH  = 64;
static constexpr int H = 512, W = 512, C = 3;
static constexpr int OUTHW  = 64;
static constexpr int NDEPTH = 3;
static constexpr int ROWFL  = W * C;   // 1536 floats per image row
static constexpr int NT     = 256;

template<int K> struct Cfg;
template<> struct Cfg<1> { static constexpr int TILE_I = 8; static constexpr int JW = 64; static constexpr int ROWF = 204; static constexpr int NV = 3; };
template<> struct Cfg<2> { static constexpr int TILE_I = 4; static constexpr int JW = 64; static constexpr int ROWF = 396; static constexpr int NV = 3; };
template<> struct Cfg<4> { static constexpr int TILE_I = 2; static constexpr int JW = 32; static constexpr int ROWF = 396; static constexpr int NV = 5; };
// IR = TILE_I*K + 1 = 9 input rows for every depth; x-span = JW*K+1 <= 129 pixels.

static constexpr int NBLK4 = BATCH * (OUTHW / Cfg<4>::TILE_I) * (OUTHW / Cfg<4>::JW); // 4096
static constexpr int NBLK2 = BATCH * (OUTHW / Cfg<2>::TILE_I);                        // 1024
static constexpr int NBLK1 = BATCH * (OUTHW / Cfg<1>::TILE_I);                        // 512
static constexpr int NBLK  = NBLK4 + NBLK2 + NBLK1;                                   // 5632

// SMEM: [0,16) mbar | tile IR*ROWF floats | hs IR*JW float4. Max over variants (K=2).
static constexpr int SMEM_BYTES = 16 + 9 * 396 * 4 + 9 * 64 * 16;   // 23488

__device__ __forceinline__ uint32_t smem_u32(const void* p) {
    return (uint32_t)__cvta_generic_to_shared(p);
}
__device__ __forceinline__ void mbar_init(uint32_t a, uint32_t cnt) {
    asm volatile("mbarrier.init.shared.b64 [%0], %1;" :: "r"(a), "r"(cnt) : "memory");
}
__device__ __forceinline__ void mbar_expect_tx(uint32_t a, uint32_t bytes) {
    asm volatile("mbarrier.arrive.expect_tx.shared.b64 _, [%0], %1;" :: "r"(a), "r"(bytes) : "memory");
}
__device__ __forceinline__ void mbar_wait(uint32_t a, uint32_t parity) {
    asm volatile(
        "{\n\t"
        ".reg .pred P;\n\t"
        "LAB_WAIT_%=:\n\t"
        "mbarrier.try_wait.parity.acquire.cta.shared::cta.b64 P, [%0], %1, 0x989680;\n\t"
        "@P bra LAB_DONE_%=;\n\t"
        "bra LAB_WAIT_%=;\n\t"
        "LAB_DONE_%=:\n\t"
        "}"
        :: "r"(a), "r"(parity) : "memory");
}
__device__ __forceinline__ void bulk_g2s(uint32_t dst, const void* src, uint32_t bytes, uint32_t mbar) {
    asm volatile(
        "cp.async.bulk.shared::cluster.global.mbarrier::complete_tx::bytes [%0], [%1], %2, [%3];"
        :: "r"(dst), "l"(src), "r"(bytes), "r"(mbar) : "memory");
}

// Horizontal weighted sum for one (row, j): window of K+1 pixels x 3 channels.
// SH = sub-float4 shift (compile-time so v[] stays in registers).
template<int K, int SH>
__device__ __forceinline__ void hreduce_one(const float* __restrict__ rowp, float wx, float4& h)
{
    constexpr int NV = Cfg<K>::NV;
    const float hx0 = 1.0f - wx;
    float v[4 * NV];
    const float4* rp = reinterpret_cast<const float4*>(rowp);
#pragma unroll
    for (int t = 0; t < NV; t++) {
        float4 q = rp[t];
        v[4*t+0] = q.x; v[4*t+1] = q.y; v[4*t+2] = q.z; v[4*t+3] = q.w;
    }
    float r0 = hx0 * v[SH + 0] + wx * v[SH + 3*K + 0];
    float r1 = hx0 * v[SH + 1] + wx * v[SH + 3*K + 1];
    float r2 = hx0 * v[SH + 2] + wx * v[SH + 3*K + 2];
#pragma unroll
    for (int q = 1; q < K; q++) {
        r0 += v[SH + 3*q + 0];
        r1 += v[SH + 3*q + 1];
        r2 += v[SH + 3*q + 2];
    }
    h.x = r0; h.y = r1; h.z = r2; h.w = 0.0f;
}

template<int K, int D>
__device__ __forceinline__ void glimpse_body(
    const float* __restrict__ img, const float* __restrict__ offs,
    float* __restrict__ out, float* smem, int b, int i0, int j0)
{
    constexpr int TILE_I = Cfg<K>::TILE_I;
    constexpr int JW     = Cfg<K>::JW;
    constexpr int RF     = Cfg<K>::ROWF;
    constexpr int IR     = TILE_I * K + 1;      // 9
    constexpr int SPAN   = JW * K + 1;          // input pixel span across x

    float* tile = smem + 4;                     // smem[0..3] holds the mbarrier
    float4* hs  = reinterpret_cast<float4*>(smem + 4 + IR * RF);
    const uint32_t mbar = smem_u32(smem);
    const int tid = threadIdx.x;

    // Per-batch geometry (fp32 ops round identically to the reference lattice)
    const float cy = (offs[2*b + 0] + 1.0f) * (H * 0.5f);
    const float cx = (offs[2*b + 1] + 1.0f) * (W * 0.5f);
    const float Ey = cy - (OUTHW * K - 1) * 0.5f;
    const float Ex = cx - (OUTHW * K - 1) * 0.5f;
    const int   y0 = (int)floorf(Ey);
    const int   x0 = (int)floorf(Ex);
    const float wy = Ey - (float)y0;
    const float wx = Ex - (float)x0;

    // This block's x-window starts at pixel px0; staging window 16B-aligned, clipped.
    const int px0     = x0 + j0 * K;
    const int x_hi    = min(px0 + SPAN, W);
    const int start_f = (px0 * 3) & ~3;
    const int end_f   = min((x_hi * 3 + 3) & ~3, ROWFL);
    const int validf  = end_f - start_f;
    const int off0    = px0 * 3 - start_f;      // 0..3
    const int rowbytes = validf * 4;            // multiple of 16
    const int ytop    = y0 + i0 * K;

    if (tid == 0) {
        mbar_init(mbar, 1);
        asm volatile("fence.proxy.async.shared::cta;" ::: "memory");
    }
    __syncthreads();

    if (tid == 0) {
        int nvalid = 0;
#pragma unroll
        for (int r = 0; r < IR; r++) if (ytop + r < H) nvalid++;
        mbar_expect_tx(mbar, (uint32_t)(nvalid * rowbytes));
#pragma unroll
        for (int r = 0; r < IR; r++) {
            const int gy = ytop + r;
            if (gy < H) {
                const float* src = img + ((size_t)b * H + gy) * ROWFL + start_f;
                bulk_g2s(smem_u32(tile + r * RF), src, (uint32_t)rowbytes, mbar);
            }
        }
    }

    // Zero tails (disjoint from bulk-copy bytes) and any y>=H rows.
    {
        const int ntail = RF - validf;          // >= 3 always
        for (int idx = tid; idx < IR * ntail; idx += NT) {
            const int r = idx / ntail;
            tile[r * RF + validf + idx % ntail] = 0.0f;
        }
#pragma unroll
        for (int r = 0; r < IR; r++) {
            if (ytop + r >= H) {
                for (int f = tid; f < validf; f += NT) tile[r * RF + f] = 0.0f;
            }
        }
    }

    mbar_wait(mbar, 0);
    __syncthreads();

    // ── Phase A: horizontal reduction, one thread per (row, j). Conflict-free
    //    (lane word-stride 3K = 12/6/3 -> distinct banks per LDS.128 phase). ──
    {
        for (int idx = tid; idx < IR * JW; idx += NT) {
            const int r = idx / JW;
            const int j = idx % JW;
            const int sidx = off0 + 3 * K * j;
            const int a0   = sidx & ~3;
            const float* rowp = tile + r * RF + a0;
            float4 h;
            switch (sidx & 3) {
            case 0:  hreduce_one<K,0>(rowp, wx, h); break;
            case 1:  hreduce_one<K,1>(rowp, wx, h); break;
            case 2:  hreduce_one<K,2>(rowp, wx, h); break;
            default: hreduce_one<K,3>(rowp, wx, h); break;
            }
            hs[r * JW + j] = h;
        }
    }
    __syncthreads();

    // ── Phase B: vertical reduction over hs. Conflict-free. ──
    constexpr float inv = 1.0f / (K * K);
    const float wy0 = 1.0f - wy;
    for (int o = tid; o < TILE_I * JW; o += NT) {
        const int ti = o / JW;
        const int j  = o % JW;
        float4 a = hs[(ti * K) * JW + j];
        float o0 = wy0 * a.x, o1 = wy0 * a.y, o2 = wy0 * a.z;
#pragma unroll
        for (int p = 1; p < K; p++) {
            float4 m = hs[(ti * K + p) * JW + j];
            o0 += m.x; o1 += m.y; o2 += m.z;
        }
        float4 e = hs[(ti * K + K) * JW + j];
        o0 += wy * e.x; o1 += wy * e.y; o2 += wy * e.z;

        const size_t ob = (((size_t)b * OUTHW + (i0 + ti)) * OUTHW + (j0 + j)) * (C * NDEPTH);
        out[ob + 0 * NDEPTH + D] = o0 * inv;
        out[ob + 1 * NDEPTH + D] = o1 * inv;
        out[ob + 2 * NDEPTH + D] = o2 * inv;
    }
}

__global__ __launch_bounds__(NT)
void glimpse_fused(const float* __restrict__ img, const float* __restrict__ offs,
                   float* __restrict__ out)
{
    extern __shared__ float smem[];
    const int bid = blockIdx.x;
    if (bid < NBLK4) {                                   // K=4: 64 blocks/image (32 row x 2 col)
        const int b = bid >> 6;
        const int t = bid & 63;
        glimpse_body<4, 2>(img, offs, out, smem, b, (t >> 1) * Cfg<4>::TILE_I, (t & 1) * Cfg<4>::JW);
    } else if (bid < NBLK4 + NBLK2) {                    // K=2: 16 blocks/image
        const int r = bid - NBLK4;
        glimpse_body<2, 1>(img, offs, out, smem, r >> 4, (r & 15) * Cfg<2>::TILE_I, 0);
    } else {                                             // K=1: 8 blocks/image
        const int r = bid - (NBLK4 + NBLK2);
        glimpse_body<1, 0>(img, offs, out, smem, r >> 3, (r & 7) * Cfg<1>::TILE_I, 0);
    }
}

extern "C" void kernel_launch(void* const* d_in, const int* in_sizes, int n_in,
                              void* d_out, int out_size)
{
    (void)in_sizes; (void)n_in; (void)out_size;
    const float* img  = (const float*)d_in[0];
    const float* offs = (const float*)d_in[1];
    float* out = (float*)d_out;

    cudaFuncSetAttribute(glimpse_fused, cudaFuncAttributeMaxDynamicSharedMemorySize, SMEM_BYTES);
    glimpse_fused<<<NBLK, NT, SMEM_BYTES>>>(img, offs, out);
}

// round 7
// speedup vs baseline: 2.9891x; 1.0311x over previous
#include <cuda_runtime.h>
#include <cstdint>
#include <math.h>

// SpatialGlimpse fused, one-shot blocks, two-phase separable stencil.
// R7: warp-0-only mbarrier wait (kills 8-warp spin), copies issued before any
// block-wide sync. Tiling identical to R6 (8 CTAs/SM, 5632 blocks, K=4 first).

static constexpr int BATCH  = 64;
static constexpr int H = 512, W = 512, C = 3;
static constexpr int OUTHW  = 64;
static constexpr int NDEPTH = 3;
static constexpr int ROWFL  = W * C;   // 1536 floats per image row
static constexpr int NT     = 256;

template<int K> struct Cfg;
template<> struct Cfg<1> { static constexpr int TILE_I = 8; static constexpr int JW = 64; static constexpr int ROWF = 204; static constexpr int NV = 3; };
template<> struct Cfg<2> { static constexpr int TILE_I = 4; static constexpr int JW = 64; static constexpr int ROWF = 396; static constexpr int NV = 3; };
template<> struct Cfg<4> { static constexpr int TILE_I = 2; static constexpr int JW = 32; static constexpr int ROWF = 396; static constexpr int NV = 5; };
// IR = TILE_I*K + 1 = 9 input rows for every depth; x-span = JW*K+1 <= 129 pixels.

static constexpr int NBLK4 = BATCH * (OUTHW / Cfg<4>::TILE_I) * (OUTHW / Cfg<4>::JW); // 4096
static constexpr int NBLK2 = BATCH * (OUTHW / Cfg<2>::TILE_I);                        // 1024
static constexpr int NBLK1 = BATCH * (OUTHW / Cfg<1>::TILE_I);                        // 512
static constexpr int NBLK  = NBLK4 + NBLK2 + NBLK1;                                   // 5632

// SMEM: [0,16) mbar | tile IR*ROWF floats | hs IR*JW float4. Max over variants (K=2).
static constexpr int SMEM_BYTES = 16 + 9 * 396 * 4 + 9 * 64 * 16;   // 23488

__device__ __forceinline__ uint32_t smem_u32(const void* p) {
    return (uint32_t)__cvta_generic_to_shared(p);
}
__device__ __forceinline__ void mbar_init(uint32_t a, uint32_t cnt) {
    asm volatile("mbarrier.init.shared.b64 [%0], %1;" :: "r"(a), "r"(cnt) : "memory");
}
__device__ __forceinline__ void mbar_expect_tx(uint32_t a, uint32_t bytes) {
    asm volatile("mbarrier.arrive.expect_tx.shared.b64 _, [%0], %1;" :: "r"(a), "r"(bytes) : "memory");
}
__device__ __forceinline__ void mbar_wait(uint32_t a, uint32_t parity) {
    asm volatile(
        "{\n\t"
        ".reg .pred P;\n\t"
        "LAB_WAIT_%=:\n\t"
        "mbarrier.try_wait.parity.acquire.cta.shared::cta.b64 P, [%0], %1, 0x989680;\n\t"
        "@P bra LAB_DONE_%=;\n\t"
        "bra LAB_WAIT_%=;\n\t"
        "LAB_DONE_%=:\n\t"
        "}"
        :: "r"(a), "r"(parity) : "memory");
}
__device__ __forceinline__ void bulk_g2s(uint32_t dst, const void* src, uint32_t bytes, uint32_t mbar) {
    asm volatile(
        "cp.async.bulk.shared::cluster.global.mbarrier::complete_tx::bytes [%0], [%1], %2, [%3];"
        :: "r"(dst), "l"(src), "r"(bytes), "r"(mbar) : "memory");
}

// Horizontal weighted sum for one (row, j): window of K+1 pixels x 3 channels.
// SH = sub-float4 shift (compile-time so v[] stays in registers).
template<int K, int SH>
__device__ __forceinline__ void hreduce_one(const float* __restrict__ rowp, float wx, float4& h)
{
    constexpr int NV = Cfg<K>::NV;
    const float hx0 = 1.0f - wx;
    float v[4 * NV];
    const float4* rp = reinterpret_cast<const float4*>(rowp);
#pragma unroll
    for (int t = 0; t < NV; t++) {
        float4 q = rp[t];
        v[4*t+0] = q.x; v[4*t+1] = q.y; v[4*t+2] = q.z; v[4*t+3] = q.w;
    }
    float r0 = hx0 * v[SH + 0] + wx * v[SH + 3*K + 0];
    float r1 = hx0 * v[SH + 1] + wx * v[SH + 3*K + 1];
    float r2 = hx0 * v[SH + 2] + wx * v[SH + 3*K + 2];
#pragma unroll
    for (int q = 1; q < K; q++) {
        r0 += v[SH + 3*q + 0];
        r1 += v[SH + 3*q + 1];
        r2 += v[SH + 3*q + 2];
    }
    h.x = r0; h.y = r1; h.z = r2; h.w = 0.0f;
}

template<int K, int D>
__device__ __forceinline__ void glimpse_body(
    const float* __restrict__ img, const float* __restrict__ offs,
    float* __restrict__ out, float* smem, int b, int i0, int j0)
{
    constexpr int TILE_I = Cfg<K>::TILE_I;
    constexpr int JW     = Cfg<K>::JW;
    constexpr int RF     = Cfg<K>::ROWF;
    constexpr int IR     = TILE_I * K + 1;      // 9
    constexpr int SPAN   = JW * K + 1;          // input pixel span across x

    float* tile = smem + 4;                     // smem[0..3] holds the mbarrier
    float4* hs  = reinterpret_cast<float4*>(smem + 4 + IR * RF);
    const uint32_t mbar = smem_u32(smem);
    const int tid = threadIdx.x;

    // Per-batch geometry (fp32 ops round identically to the reference lattice)
    const float cy = (offs[2*b + 0] + 1.0f) * (H * 0.5f);
    const float cx = (offs[2*b + 1] + 1.0f) * (W * 0.5f);
    const float Ey = cy - (OUTHW * K - 1) * 0.5f;
    const float Ex = cx - (OUTHW * K - 1) * 0.5f;
    const int   y0 = (int)floorf(Ey);
    const int   x0 = (int)floorf(Ex);
    const float wy = Ey - (float)y0;
    const float wx = Ex - (float)x0;

    // This block's x-window starts at pixel px0; staging window 16B-aligned, clipped.
    const int px0     = x0 + j0 * K;
    const int x_hi    = min(px0 + SPAN, W);
    const int start_f = (px0 * 3) & ~3;
    const int end_f   = min((x_hi * 3 + 3) & ~3, ROWFL);
    const int validf  = end_f - start_f;
    const int off0    = px0 * 3 - start_f;      // 0..3
    const int rowbytes = validf * 4;            // multiple of 16
    const int ytop    = y0 + i0 * K;
    const int nvalid  = min(H - ytop, IR) - max(0, -ytop);  // rows with 0<=gy<H (contiguous)

    // tid0 inits the mbar and fires all bulk copies immediately; no block sync
    // needed first — only tid0 touches the mbar until the post-zeroing barrier.
    if (tid == 0) {
        mbar_init(mbar, 1);
        asm volatile("fence.proxy.async.shared::cta;" ::: "memory");
        mbar_expect_tx(mbar, (uint32_t)(nvalid * rowbytes));
#pragma unroll
        for (int r = 0; r < IR; r++) {
            const int gy = ytop + r;
            if ((unsigned)gy < (unsigned)H) {
                const float* src = img + ((size_t)b * H + gy) * ROWFL + start_f;
                bulk_g2s(smem_u32(tile + r * RF), src, (uint32_t)rowbytes, mbar);
            }
        }
    }

    // Meanwhile: zero tails (disjoint from bulk-copy dest bytes) and OOB rows.
    {
        const int ntail = RF - validf;          // >= 3 always
        for (int idx = tid; idx < IR * ntail; idx += NT) {
            const int r = idx / ntail;
            tile[r * RF + validf + idx % ntail] = 0.0f;
        }
#pragma unroll
        for (int r = 0; r < IR; r++) {
            if ((unsigned)(ytop + r) >= (unsigned)H) {
                for (int f = tid; f < validf; f += NT) tile[r * RF + f] = 0.0f;
            }
        }
    }

    __syncthreads();                 // zeros done + mbar init visible to warp 0
    if (tid < 32) mbar_wait(mbar, 0);   // single-warp wait: no 8-warp spin
    __syncthreads();

    // ── Phase A: horizontal reduction, one thread per (row, j). Conflict-free
    //    (lane word-stride 3K = 12/6/3 -> distinct banks per LDS.128 phase). ──
    {
        for (int idx = tid; idx < IR * JW; idx += NT) {
            const int r = idx / JW;
            const int j = idx % JW;
            const int sidx = off0 + 3 * K * j;
            const int a0   = sidx & ~3;
            const float* rowp = tile + r * RF + a0;
            float4 h;
            switch (sidx & 3) {
            case 0:  hreduce_one<K,0>(rowp, wx, h); break;
            case 1:  hreduce_one<K,1>(rowp, wx, h); break;
            case 2:  hreduce_one<K,2>(rowp, wx, h); break;
            default: hreduce_one<K,3>(rowp, wx, h); break;
            }
            hs[r * JW + j] = h;
        }
    }
    __syncthreads();

    // ── Phase B: vertical reduction over hs. Conflict-free. ──
    constexpr float inv = 1.0f / (K * K);
    const float wy0 = 1.0f - wy;
    for (int o = tid; o < TILE_I * JW; o += NT) {
        const int ti = o / JW;
        const int j  = o % JW;
        float4 a = hs[(ti * K) * JW + j];
        float o0 = wy0 * a.x, o1 = wy0 * a.y, o2 = wy0 * a.z;
#pragma unroll
        for (int p = 1; p < K; p++) {
            float4 m = hs[(ti * K + p) * JW + j];
            o0 += m.x; o1 += m.y; o2 += m.z;
        }
        float4 e = hs[(ti * K + K) * JW + j];
        o0 += wy * e.x; o1 += wy * e.y; o2 += wy * e.z;

        const size_t ob = (((size_t)b * OUTHW + (i0 + ti)) * OUTHW + (j0 + j)) * (C * NDEPTH);
        out[ob + 0 * NDEPTH + D] = o0 * inv;
        out[ob + 1 * NDEPTH + D] = o1 * inv;
        out[ob + 2 * NDEPTH + D] = o2 * inv;
    }
}

__global__ __launch_bounds__(NT)
void glimpse_fused(const float* __restrict__ img, const float* __restrict__ offs,
                   float* __restrict__ out)
{
    extern __shared__ float smem[];
    const int bid = blockIdx.x;
    if (bid < NBLK4) {                                   // K=4: 64 blocks/image (32 row x 2 col)
        const int b = bid >> 6;
        const int t = bid & 63;
        glimpse_body<4, 2>(img, offs, out, smem, b, (t >> 1) * Cfg<4>::TILE_I, (t & 1) * Cfg<4>::JW);
    } else if (bid < NBLK4 + NBLK2) {                    // K=2: 16 blocks/image
        const int r = bid - NBLK4;
        glimpse_body<2, 1>(img, offs, out, smem, r >> 4, (r & 15) * Cfg<2>::TILE_I, 0);
    } else {                                             // K=1: 8 blocks/image
        const int r = bid - (NBLK4 + NBLK2);
        glimpse_body<1, 0>(img, offs, out, smem, r >> 3, (r & 7) * Cfg<1>::TILE_I, 0);
    }
}

extern "C" void kernel_launch(void* const* d_in, const int* in_sizes, int n_in,
                              void* d_out, int out_size)
{
    (void)in_sizes; (void)n_in; (void)out_size;
    const float* img  = (const float*)d_in[0];
    const float* offs = (const float*)d_in[1];
    float* out = (float*)d_out;

    cudaFuncSetAttribute(glimpse_fused, cudaFuncAttributeMaxDynamicSharedMemorySize, SMEM_BYTES);
    glimpse_fused<<<NBLK, NT, SMEM_BYTES>>>(img, offs, out);
}